// round 11
// baseline (speedup 1.0000x reference)
#include <cuda_runtime.h>
#include <cuda_fp16.h>
#include <math.h>
#include <stdint.h>
#include <string.h>

// ArcFace fused loss. N=512, D=512, C=100000.  fp16 HMMA, prep-free W path.
//   norm_x  : x -> 92.33 * x_hat fp16 rows in g_x16; zero g_rowsum.
//   gemm    : grid = 782 CTAs (one 128-class tile each), M=512 per CTA.
//             W streamed RAW fp32 via cp.async (read once chip-wide);
//             B fragments built by LDS.64 + cvt.rn.f16x2.f32; ||w||^2
//             accumulated from the same fp32 stage and applied as packed
//             1/||w|| in the epilogue: v2 = fma.f16x2(acc, rw2, bias2),
//             bias = -16 (frame) or -inf (pad classes -> exact 0 terms),
//             then ex2.approx.f16x2. Target column patched exactly in fp32.
//   finalize: loss_i = log(rowsum_i) + 16*ln2 - tlogit_i; mean -> d_out[0]

#define N_ 512
#define D_ 512
#define C_ 100000
#define NTILES 782
#define NCHUNK 16             // K chunks of 32

#define CLIP_LO  (-1.0f + 1e-7f)
#define CLIP_HI  (1.0f - 1e-7f)
#define COS_M_   0.8775825618903728f
#define SIN_M_   0.4794255386042030f
#define TH_      (-0.8775825618903728f)
#define MM_      0.2397127693021015f
#define K2F      92.33248261778075f      // 64 / ln(2)
#define SHIFT_LN 11.090354888959125f     // 16 * ln(2)

// smem layout (bytes)
//   A stages (3): 512 rows x 80B   = 40960 each
//   W stages (3): 128 rows x 144B  = 18432 each (32 f32 + pad)
#define SA(s)   ((s) * 40960)
#define SW(s)   (122880 + (s) * 18432)
#define SM_TG   178176
#define SM_ROW  180224
#define SM_SSP  182272
#define SM_RW   183296
#define SM_RW2  183808
#define SM_B2   184064
#define SMEM_BYTES 184320

__device__ __half g_x16[N_ * D_];
__device__ float  g_rowsum[N_];
__device__ float  g_tlogit[N_];

// ------------------------------------------------------------------ helpers
__device__ __forceinline__ uint32_t smem_u32(const void* p) {
    uint32_t a;
    asm("{ .reg .u64 t; cvta.to.shared.u64 t, %1; cvt.u32.u64 %0, t; }"
        : "=r"(a) : "l"(p));
    return a;
}
__device__ __forceinline__ void cp16(uint32_t dst, const void* src) {
    asm volatile("cp.async.cg.shared.global [%0], [%1], 16;"
                 :: "r"(dst), "l"(src));
}
__device__ __forceinline__ void cp16z(uint32_t dst, const void* src, int srcsz) {
    asm volatile("cp.async.cg.shared.global [%0], [%1], 16, %2;"
                 :: "r"(dst), "l"(src), "r"(srcsz));
}
__device__ __forceinline__ uint32_t lds32(uint32_t a) {
    uint32_t v;
    asm volatile("ld.shared.b32 %0, [%1];" : "=r"(v) : "r"(a));
    return v;
}
__device__ __forceinline__ float2 lds_f32x2(uint32_t a) {
    float2 v;
    asm volatile("ld.shared.v2.f32 {%0,%1}, [%2];" : "=f"(v.x), "=f"(v.y) : "r"(a));
    return v;
}
__device__ __forceinline__ float4 lds_f32x4(uint32_t a) {
    float4 v;
    asm volatile("ld.shared.v4.f32 {%0,%1,%2,%3}, [%4];"
                 : "=f"(v.x), "=f"(v.y), "=f"(v.z), "=f"(v.w) : "r"(a));
    return v;
}
__device__ __forceinline__ void mma_f16acc(uint32_t* d, const uint32_t* a,
                                           const uint32_t* b) {
    asm volatile(
        "mma.sync.aligned.m16n8k16.row.col.f16.f16.f16.f16 "
        "{%0,%1}, {%2,%3,%4,%5}, {%6,%7}, {%0,%1};"
        : "+r"(d[0]), "+r"(d[1])
        : "r"(a[0]), "r"(a[1]), "r"(a[2]), "r"(a[3]), "r"(b[0]), "r"(b[1]));
}
__device__ __forceinline__ uint32_t h2_bits(__half2 h) {
    uint32_t u; memcpy(&u, &h, 4); return u;
}
__device__ __forceinline__ uint32_t hadd2(uint32_t a, uint32_t b) {
    uint32_t d; asm("add.rn.f16x2 %0, %1, %2;" : "=r"(d) : "r"(a), "r"(b)); return d;
}
__device__ __forceinline__ uint32_t hfma2_(uint32_t a, uint32_t b, uint32_t c) {
    uint32_t d; asm("fma.rn.f16x2 %0, %1, %2, %3;" : "=r"(d) : "r"(a), "r"(b), "r"(c));
    return d;
}
__device__ __forceinline__ uint32_t ex2_h2(uint32_t a) {
    uint32_t d; asm("ex2.approx.f16x2 %0, %1;" : "=r"(d) : "r"(a)); return d;
}
__device__ __forceinline__ uint32_t swap16(uint32_t a) {
    uint32_t d; asm("prmt.b32 %0, %1, %1, 0x1032;" : "=r"(d) : "r"(a)); return d;
}
__device__ __forceinline__ uint32_t pack_h2(float v0, float v1) {
    uint32_t d;
    asm("cvt.rn.f16x2.f32 %0, %1, %2;" : "=r"(d) : "f"(v1), "f"(v0));  // v0 -> low
    return d;
}

// ---------------------------------------------------------------------------
// norm_x: 256 blocks x 2 rows; writes 92.33 * x_hat fp16; zeroes g_rowsum
// ---------------------------------------------------------------------------
__global__ void norm_x_kernel(const float* __restrict__ x) {
    int sub = threadIdx.x >> 7;
    int row = blockIdx.x * 2 + sub;
    int t   = threadIdx.x & 127;
    if (t == 0) g_rowsum[row] = 0.0f;
    float4 v = *(const float4*)(x + (size_t)row * D_ + t * 4);
    float ss = v.x * v.x + v.y * v.y + v.z * v.z + v.w * v.w;
    #pragma unroll
    for (int o = 16; o; o >>= 1) ss += __shfl_xor_sync(0xffffffffu, ss, o);
    __shared__ float sm[2][4];
    if ((t & 31) == 0) sm[sub][t >> 5] = ss;
    __syncthreads();
    float inv = K2F / fmaxf(sqrtf(sm[sub][0] + sm[sub][1] + sm[sub][2] + sm[sub][3]), 1e-12f);
    uint2* dst = (uint2*)(g_x16 + (size_t)row * D_);
    uint2 o2;
    o2.x = pack_h2(v.x * inv, v.y * inv);
    o2.y = pack_h2(v.z * inv, v.w * inv);
    dst[t] = o2;
}

// ---------------------------------------------------------------------------
__global__ void __launch_bounds__(256, 1)
arcface_gemm_kernel(const float* __restrict__ w, const int* __restrict__ target) {
    extern __shared__ __align__(16) char smem[];
    const uint32_t sb = smem_u32(smem);
    int*   tg     = (int*)(smem + SM_TG);
    float* rowacc = (float*)(smem + SM_ROW);
    float* ssp    = (float*)(smem + SM_SSP);
    float* rwsm   = (float*)(smem + SM_RW);
    uint32_t* rw2sm = (uint32_t*)(smem + SM_RW2);
    uint32_t* b2sm  = (uint32_t*)(smem + SM_B2);

    const int tid  = threadIdx.x;
    const int lane = tid & 31;
    const int wid  = tid >> 5;         // 8 warps: 64-row M-slabs
    const int gid  = lane >> 2;
    const int tig  = lane & 3;
    const int c0   = blockIdx.x * 128;

    tg[tid]       = target[tid];
    tg[tid + 256] = target[tid + 256];
    rowacc[tid]         = 0.0f;
    rowacc[tid + 256]   = 0.0f;

    // per-lane fragment base offsets
    const uint32_t aOff = (uint32_t)((wid * 64 + gid) * 80 + tig * 4);
    const uint32_t wOff = (uint32_t)(gid * 144 + tig * 8);
    // ssq pass coords
    const int srow  = tid >> 1;
    const int shalf = tid & 1;

    uint32_t acc[4][16][2];
    #pragma unroll
    for (int mi = 0; mi < 4; mi++)
        #pragma unroll
        for (int ni = 0; ni < 16; ni++) {
            acc[mi][ni][0] = 0u; acc[mi][ni][1] = 0u;
        }

    auto load_chunk = [&](int c, int s) {
        const __half* asrc = g_x16 + c * 32;
        #pragma unroll
        for (int i = 0; i < 8; i++) {           // A: 512 rows x 4 granules
            int g = i * 256 + tid, row = g >> 2, q = g & 3;
            cp16(sb + SA(s) + row * 80 + q * 16, asrc + (size_t)row * D_ + q * 8);
        }
        #pragma unroll
        for (int i = 0; i < 4; i++) {           // W fp32: 128 rows x 8 granules
            int g = i * 256 + tid, row = g >> 3, q = g & 7;
            int cls = c0 + row;
            int ok = (cls < C_) ? 16 : 0;
            const float* src = w + (size_t)(ok ? cls : 0) * D_ + c * 32 + q * 4;
            cp16z(sb + SW(s) + row * 144 + q * 16, src, ok);
        }
        asm volatile("cp.async.commit_group;" ::: "memory");
    };

    load_chunk(0, 0);
    load_chunk(1, 1);

    float ssq = 0.0f;

    #pragma unroll 1
    for (int c = 0; c < NCHUNK; c++) {
        const int s = c - (c / 3) * 3;          // c % 3
        asm volatile("cp.async.wait_group 1;" ::: "memory");
        __syncthreads();
        if (c + 2 < NCHUNK) {
            int s2i = (c + 2) - ((c + 2) / 3) * 3;
            load_chunk(c + 2, s2i);
        } else {
            asm volatile("cp.async.commit_group;" ::: "memory");
        }

        const uint32_t A = sb + SA(s) + aOff;
        const uint32_t W = sb + SW(s);

        // fused ||w||^2 partials from the live fp32 stage
        {
            uint32_t base = W + srow * 144 + shalf * 64;
            #pragma unroll
            for (int q = 0; q < 4; q++) {
                float4 v = lds_f32x4(base + q * 16);
                ssq += v.x * v.x + v.y * v.y + v.z * v.z + v.w * v.w;
            }
        }

        #pragma unroll
        for (int k2 = 0; k2 < 2; k2++) {
            uint32_t af[4][4];
            #pragma unroll
            for (int mi = 0; mi < 4; mi++) {
                uint32_t o = A + mi * 1280 + k2 * 32;
                af[mi][0] = lds32(o);
                af[mi][1] = lds32(o + 640);
                af[mi][2] = lds32(o + 16);
                af[mi][3] = lds32(o + 656);
            }
            #pragma unroll
            for (int ni = 0; ni < 16; ni++) {
                uint32_t wb = W + ni * 1152 + wOff + k2 * 64;
                float2 lo = lds_f32x2(wb);
                float2 hi = lds_f32x2(wb + 32);
                uint32_t bf[2];
                bf[0] = pack_h2(lo.x, lo.y);
                bf[1] = pack_h2(hi.x, hi.y);
                #pragma unroll
                for (int mi = 0; mi < 4; mi++)
                    mma_f16acc(acc[mi][ni], af[mi], bf);
            }
        }
    }

    // ---- build per-class 1/||w|| and bias tables -------------------------
    ssp[tid] = ssq;
    __syncthreads();
    if (tid < 128) {
        float s = ssp[2 * tid] + ssp[2 * tid + 1];
        rwsm[tid] = (s > 0.0f) ? rsqrtf(s) : 0.0f;
    }
    __syncthreads();
    if (tid < 64) {
        rw2sm[tid] = pack_h2(rwsm[2 * tid], rwsm[2 * tid + 1]);
        uint32_t bl = (c0 + 2 * tid     < C_) ? 0xCC00u : 0xFC00u;  // -16 : -inf
        uint32_t bh = (c0 + 2 * tid + 1 < C_) ? 0xCC00u : 0xFC00u;
        b2sm[tid] = bl | (bh << 16);
    }
    __syncthreads();

    uint32_t rw2p[16], b2p[16];
    #pragma unroll
    for (int ni = 0; ni < 16; ni++) {
        rw2p[ni] = rw2sm[ni * 4 + tig];
        b2p[ni]  = b2sm[ni * 4 + tig];
    }

    // ---- epilogue ---------------------------------------------------------
    #pragma unroll
    for (int mi = 0; mi < 4; mi++) {
        #pragma unroll
        for (int h = 0; h < 2; h++) {
            const int r = wid * 64 + mi * 16 + h * 8 + gid;   // global row
            const int lc = tg[r] - c0;

            if ((unsigned)lc < 128u && ((lc >> 1) & 3) == tig) {
                const int nt = lc >> 3, j = lc & 1;
                uint32_t reg = acc[mi][nt][h];
                __half2 hv; memcpy(&hv, &reg, 4);
                float av = j ? __high2float(hv) : __low2float(hv);
                float rwc = rwsm[lc];
                float cv = av * rwc * (1.0f / K2F);
                cv = fminf(fmaxf(cv, CLIP_LO), CLIP_HI);
                float t = fminf(fmaxf(1.0f - cv * cv, CLIP_LO), CLIP_HI);
                float phi = cv * COS_M_ - sqrtf(t) * SIN_M_;
                if (!(cv > TH_)) phi = cv - MM_;
                g_tlogit[r] = phi * 64.0f;
                __half hp = __float2half_rn(phi * K2F / rwc);
                if (j) hv = __halves2half2(__low2half(hv), hp);
                else   hv = __halves2half2(hp, __high2half(hv));
                memcpy(&reg, &hv, 4);
                acc[mi][nt][h] = reg;
            }

            uint32_t s2 = 0;
            #pragma unroll
            for (int ni = 0; ni < 16; ni++)
                s2 = hadd2(s2, ex2_h2(hfma2_(acc[mi][ni][h], rw2p[ni], b2p[ni])));
            s2 = hadd2(s2, swap16(s2));
            __half2 sh; memcpy(&sh, &s2, 4);
            float p = __low2float(sh);
            p += __shfl_xor_sync(0xffffffffu, p, 1);
            p += __shfl_xor_sync(0xffffffffu, p, 2);
            if (tig == 0) atomicAdd(&rowacc[r], p);
        }
    }
    __syncthreads();
    atomicAdd(&g_rowsum[tid],       rowacc[tid]);
    atomicAdd(&g_rowsum[tid + 256], rowacc[tid + 256]);
}

// ---------------------------------------------------------------------------
__global__ void finalize_kernel(float* __restrict__ out) {
    int i = threadIdx.x;   // 512
    float v = logf(g_rowsum[i]) + SHIFT_LN - g_tlogit[i];
    #pragma unroll
    for (int o = 16; o; o >>= 1) v += __shfl_xor_sync(0xffffffffu, v, o);
    __shared__ float sm[16];
    if ((i & 31) == 0) sm[i >> 5] = v;
    __syncthreads();
    if (i < 16) {
        float t = sm[i];
        #pragma unroll
        for (int o = 8; o; o >>= 1) t += __shfl_xor_sync(0x0000ffffu, t, o);
        if (i == 0) out[0] = t * (1.0f / (float)N_);
    }
}

// ---------------------------------------------------------------------------
extern "C" void kernel_launch(void* const* d_in, const int* in_sizes, int n_in,
                              void* d_out, int out_size) {
    const float* x   = (const float*)d_in[0];   // [512, 512] fp32
    const int*   tgt = (const int*)d_in[1];     // [512] int32
    const float* w   = (const float*)d_in[2];   // [100000, 512] fp32

    static int smem_set = 0;
    if (!smem_set) {
        cudaFuncSetAttribute(arcface_gemm_kernel,
                             cudaFuncAttributeMaxDynamicSharedMemorySize, SMEM_BYTES);
        smem_set = 1;
    }

    norm_x_kernel<<<256, 256>>>(x);
    arcface_gemm_kernel<<<NTILES, 256, SMEM_BYTES>>>(w, tgt);
    finalize_kernel<<<1, N_>>>((float*)d_out);
}

// round 12
// speedup vs baseline: 2.1415x; 2.1415x over previous
#include <cuda_runtime.h>
#include <cuda_fp16.h>
#include <math.h>
#include <stdint.h>
#include <string.h>

// ArcFace fused loss. N=512, D=512, C=100000.  fp16 HMMA, prep-free.
//   norm_x  : x -> 92.33 * x_hat fp16 rows in g_x16; zero g_rowsum.
//   gemm    : grid (4, 782): 128 rows x 128 classes per CTA, occupancy 2.
//             A fp16 via cp.async; W streamed RAW fp32 via cp.async into a
//             3-stage buffer, converted IN PLACE to f16 cooperatively by all
//             256 threads (Sum(w^2) accumulated for free from the registers).
//             mma.sync.m16n8k16 f16/f16-acc (acc = 92.33 * x_hat . w).
//             Epilogue: v2 = fma.f16x2(acc, rw2, bias2) where rw2 = packed
//             1/||w||, bias = -16 (frame) or -inf (pad classes -> exact 0),
//             then ex2.approx.f16x2. Target column patched exactly in fp32.
//   finalize: loss_i = log(rowsum_i) + 16*ln2 - tlogit_i; mean -> d_out[0]

#define N_ 512
#define D_ 512
#define C_ 100000
#define NCHUNK 16             // K chunks of 32

#define CLIP_LO  (-1.0f + 1e-7f)
#define CLIP_HI  (1.0f - 1e-7f)
#define COS_M_   0.8775825618903728f
#define SIN_M_   0.4794255386042030f
#define TH_      (-0.8775825618903728f)
#define MM_      0.2397127693021015f
#define K2F      92.33248261778075f      // 64 / ln(2)
#define INV_K2F  0.010830424696159f      // ln(2) / 64
#define SHIFT_LN 11.090354888959125f     // 16 * ln(2)

// smem layout (bytes)
//   A stages (3): 128 rows x 80B  = 10240 each
//   W stages (3): 128 rows x 144B = 18432 each (32 f32, converted in place)
#define SA(s)   ((s) * 10240)
#define SW(s)   (30720 + (s) * 18432)
#define SM_TG   86016
#define SM_ROW  86528
#define SM_SSP  87040
#define SM_RW   88064
#define SM_RW2  88576
#define SM_B2   88832
#define SMEM_BYTES 89088

__device__ __half g_x16[N_ * D_];
__device__ float  g_rowsum[N_];
__device__ float  g_tlogit[N_];

// ------------------------------------------------------------------ helpers
__device__ __forceinline__ uint32_t smem_u32(const void* p) {
    uint32_t a;
    asm("{ .reg .u64 t; cvta.to.shared.u64 t, %1; cvt.u32.u64 %0, t; }"
        : "=r"(a) : "l"(p));
    return a;
}
__device__ __forceinline__ void cp16(uint32_t dst, const void* src) {
    asm volatile("cp.async.cg.shared.global [%0], [%1], 16;"
                 :: "r"(dst), "l"(src));
}
__device__ __forceinline__ void cp16z(uint32_t dst, const void* src, int srcsz) {
    asm volatile("cp.async.cg.shared.global [%0], [%1], 16, %2;"
                 :: "r"(dst), "l"(src), "r"(srcsz));
}
__device__ __forceinline__ uint32_t lds32(uint32_t a) {
    uint32_t v;
    asm volatile("ld.shared.b32 %0, [%1];" : "=r"(v) : "r"(a));
    return v;
}
__device__ __forceinline__ float4 lds_f32x4(uint32_t a) {
    float4 v;
    asm volatile("ld.shared.v4.f32 {%0,%1,%2,%3}, [%4];"
                 : "=f"(v.x), "=f"(v.y), "=f"(v.z), "=f"(v.w) : "r"(a));
    return v;
}
__device__ __forceinline__ void sts128(uint32_t a, uint32_t r0, uint32_t r1,
                                       uint32_t r2, uint32_t r3) {
    asm volatile("st.shared.v4.b32 [%0], {%1,%2,%3,%4};"
                 :: "r"(a), "r"(r0), "r"(r1), "r"(r2), "r"(r3));
}
__device__ __forceinline__ void mma_f16acc(uint32_t* d, const uint32_t* a,
                                           const uint32_t* b) {
    asm volatile(
        "mma.sync.aligned.m16n8k16.row.col.f16.f16.f16.f16 "
        "{%0,%1}, {%2,%3,%4,%5}, {%6,%7}, {%0,%1};"
        : "+r"(d[0]), "+r"(d[1])
        : "r"(a[0]), "r"(a[1]), "r"(a[2]), "r"(a[3]), "r"(b[0]), "r"(b[1]));
}
__device__ __forceinline__ uint32_t hadd2(uint32_t a, uint32_t b) {
    uint32_t d; asm("add.rn.f16x2 %0, %1, %2;" : "=r"(d) : "r"(a), "r"(b)); return d;
}
__device__ __forceinline__ uint32_t hfma2_(uint32_t a, uint32_t b, uint32_t c) {
    uint32_t d; asm("fma.rn.f16x2 %0, %1, %2, %3;" : "=r"(d) : "r"(a), "r"(b), "r"(c));
    return d;
}
__device__ __forceinline__ uint32_t ex2_h2(uint32_t a) {
    uint32_t d; asm("ex2.approx.f16x2 %0, %1;" : "=r"(d) : "r"(a)); return d;
}
__device__ __forceinline__ uint32_t swap16(uint32_t a) {
    uint32_t d; asm("prmt.b32 %0, %1, %1, 0x1032;" : "=r"(d) : "r"(a)); return d;
}
__device__ __forceinline__ uint32_t pack_h2(float v0, float v1) {
    uint32_t d;
    asm("cvt.rn.f16x2.f32 %0, %1, %2;" : "=r"(d) : "f"(v1), "f"(v0));  // v0 -> low
    return d;
}

// ---------------------------------------------------------------------------
// norm_x: 256 blocks x 2 rows; writes 92.33 * x_hat fp16; zeroes g_rowsum
// ---------------------------------------------------------------------------
__global__ void norm_x_kernel(const float* __restrict__ x) {
    int sub = threadIdx.x >> 7;
    int row = blockIdx.x * 2 + sub;
    int t   = threadIdx.x & 127;
    if (t == 0) g_rowsum[row] = 0.0f;
    float4 v = *(const float4*)(x + (size_t)row * D_ + t * 4);
    float ss = v.x * v.x + v.y * v.y + v.z * v.z + v.w * v.w;
    #pragma unroll
    for (int o = 16; o; o >>= 1) ss += __shfl_xor_sync(0xffffffffu, ss, o);
    __shared__ float sm[2][4];
    if ((t & 31) == 0) sm[sub][t >> 5] = ss;
    __syncthreads();
    float inv = K2F / fmaxf(sqrtf(sm[sub][0] + sm[sub][1] + sm[sub][2] + sm[sub][3]), 1e-12f);
    uint2* dst = (uint2*)(g_x16 + (size_t)row * D_);
    uint2 o2;
    o2.x = pack_h2(v.x * inv, v.y * inv);
    o2.y = pack_h2(v.z * inv, v.w * inv);
    dst[t] = o2;
}

// ---------------------------------------------------------------------------
__global__ void __launch_bounds__(256, 2)
arcface_gemm_kernel(const float* __restrict__ w, const int* __restrict__ target) {
    extern __shared__ __align__(16) char smem[];
    const uint32_t sb = smem_u32(smem);
    int*      tg     = (int*)(smem + SM_TG);
    float*    rowacc = (float*)(smem + SM_ROW);
    float*    ssp    = (float*)(smem + SM_SSP);
    float*    rwsm   = (float*)(smem + SM_RW);
    uint32_t* rw2sm  = (uint32_t*)(smem + SM_RW2);
    uint32_t* b2sm   = (uint32_t*)(smem + SM_B2);

    const int tid  = threadIdx.x;
    const int lane = tid & 31;
    const int wid  = tid >> 5;
    const int wm   = wid >> 2;          // 64-row slab
    const int wn   = wid & 3;           // 32-col slab
    const int gid  = lane >> 2;
    const int tig  = lane & 3;
    const int row0 = blockIdx.x * 128;  // grid.x = 4 (M adjacent -> W in L2)
    const int c0   = blockIdx.y * 128;  // grid.y = 782

    if (tid < 128) {
        tg[tid]     = target[row0 + tid];
        rowacc[tid] = 0.0f;
    }

    // conversion coords: each thread owns 16 f32 of one W row
    const int crow  = tid >> 1;
    const int chalf = tid & 1;

    uint32_t acc[4][4][2];
    #pragma unroll
    for (int mi = 0; mi < 4; mi++)
        #pragma unroll
        for (int ni = 0; ni < 4; ni++) {
            acc[mi][ni][0] = 0u; acc[mi][ni][1] = 0u;
        }

    auto load_chunk = [&](int c, int s) {
        const __half* asrc = g_x16 + (size_t)row0 * D_ + c * 32;
        #pragma unroll
        for (int i = 0; i < 2; i++) {           // A: 128 rows x 4 granules
            int g = i * 256 + tid, row = g >> 2, q = g & 3;
            cp16(sb + SA(s) + row * 80 + q * 16, asrc + (size_t)row * D_ + q * 8);
        }
        #pragma unroll
        for (int i = 0; i < 4; i++) {           // W fp32: 128 rows x 8 granules
            int g = i * 256 + tid, row = g >> 3, q = g & 7;
            int cls = c0 + row;
            int ok = (cls < C_) ? 16 : 0;
            const float* src = w + (size_t)(ok ? cls : 0) * D_ + c * 32 + q * 4;
            cp16z(sb + SW(s) + row * 144 + q * 16, src, ok);
        }
        asm volatile("cp.async.commit_group;" ::: "memory");
    };

    load_chunk(0, 0);
    load_chunk(1, 1);

    float ssq = 0.0f;

    #pragma unroll 1
    for (int c = 0; c < NCHUNK; c++) {
        const int s = c - (c / 3) * 3;          // c % 3
        asm volatile("cp.async.wait_group 1;" ::: "memory");
        __syncthreads();
        if (c + 2 < NCHUNK) {
            int sn = (c + 2) - ((c + 2) / 3) * 3;
            load_chunk(c + 2, sn);
        } else {
            asm volatile("cp.async.commit_group;" ::: "memory");
        }

        const uint32_t A = sb + SA(s);
        const uint32_t W = sb + SW(s);

        // ---- cooperative in-place W conversion: read phase ---------------
        const uint32_t rbase = W + crow * 144 + chalf * 64;
        float4 v0 = lds_f32x4(rbase);
        float4 v1 = lds_f32x4(rbase + 16);
        float4 v2 = lds_f32x4(rbase + 32);
        float4 v3 = lds_f32x4(rbase + 48);
        ssq += v0.x * v0.x + v0.y * v0.y + v0.z * v0.z + v0.w * v0.w
             + v1.x * v1.x + v1.y * v1.y + v1.z * v1.z + v1.w * v1.w
             + v2.x * v2.x + v2.y * v2.y + v2.z * v2.z + v2.w * v2.w
             + v3.x * v3.x + v3.y * v3.y + v3.z * v3.z + v3.w * v3.w;
        __syncthreads();
        // ---- write phase (f16x2, first 64B of each row) -------------------
        const uint32_t wbase = W + crow * 144 + chalf * 32;
        sts128(wbase, pack_h2(v0.x, v0.y), pack_h2(v0.z, v0.w),
                       pack_h2(v1.x, v1.y), pack_h2(v1.z, v1.w));
        sts128(wbase + 16, pack_h2(v2.x, v2.y), pack_h2(v2.z, v2.w),
                            pack_h2(v3.x, v3.y), pack_h2(v3.z, v3.w));
        __syncthreads();

        // ---- MMA ----------------------------------------------------------
        #pragma unroll
        for (int kk = 0; kk < 32; kk += 16) {
            uint32_t af[4][4], bf[4][2];
            #pragma unroll
            for (int mi = 0; mi < 4; mi++) {
                uint32_t off = A + (wm * 64 + mi * 16 + gid) * 80 + kk * 2 + tig * 4;
                af[mi][0] = lds32(off);
                af[mi][1] = lds32(off + 8 * 80);
                af[mi][2] = lds32(off + 16);
                af[mi][3] = lds32(off + 8 * 80 + 16);
            }
            #pragma unroll
            for (int ni = 0; ni < 4; ni++) {
                uint32_t off = W + (wn * 32 + ni * 8 + gid) * 144 + kk * 2 + tig * 4;
                bf[ni][0] = lds32(off);
                bf[ni][1] = lds32(off + 16);
            }
            #pragma unroll
            for (int mi = 0; mi < 4; mi++)
                #pragma unroll
                for (int ni = 0; ni < 4; ni++)
                    mma_f16acc(acc[mi][ni], af[mi], bf[ni]);
        }
    }

    // ---- per-class 1/||w|| and bias tables --------------------------------
    ssp[tid] = ssq;
    __syncthreads();
    if (tid < 128) {
        float s = ssp[2 * tid] + ssp[2 * tid + 1];
        rwsm[tid] = (s > 0.0f) ? rsqrtf(s) : 0.0f;
    }
    __syncthreads();
    if (tid < 64) {
        rw2sm[tid] = pack_h2(rwsm[2 * tid], rwsm[2 * tid + 1]);
        uint32_t bl = (c0 + 2 * tid     < C_) ? 0xCC00u : 0xFC00u;  // -16 : -inf
        uint32_t bh = (c0 + 2 * tid + 1 < C_) ? 0xCC00u : 0xFC00u;
        b2sm[tid] = bl | (bh << 16);
    }
    __syncthreads();

    uint32_t rw2p[4], b2p[4];
    #pragma unroll
    for (int ni = 0; ni < 4; ni++) {
        rw2p[ni] = rw2sm[wn * 16 + ni * 4 + tig];
        b2p[ni]  = b2sm[wn * 16 + ni * 4 + tig];
    }

    // ---- epilogue ----------------------------------------------------------
    #pragma unroll
    for (int mi = 0; mi < 4; mi++) {
        #pragma unroll
        for (int h = 0; h < 2; h++) {
            const int r  = wm * 64 + mi * 16 + h * 8 + gid;
            const int gm = row0 + r;
            const int lc = tg[r] - c0;

            if ((unsigned)lc < 128u && (lc >> 5) == wn && ((lc >> 1) & 3) == tig) {
                const int nt = (lc >> 3) & 3, j = lc & 1;
                uint32_t reg = acc[mi][nt][h];
                __half2 hv; memcpy(&hv, &reg, 4);
                float av = j ? __high2float(hv) : __low2float(hv);
                float rwc = rwsm[lc];
                float cv = av * rwc * INV_K2F;
                cv = fminf(fmaxf(cv, CLIP_LO), CLIP_HI);
                float t = fminf(fmaxf(1.0f - cv * cv, CLIP_LO), CLIP_HI);
                float phi = cv * COS_M_ - sqrtf(t) * SIN_M_;
                if (!(cv > TH_)) phi = cv - MM_;
                g_tlogit[gm] = phi * 64.0f;
                __half hp = __float2half_rn(phi * K2F / rwc);
                if (j) hv = __halves2half2(__low2half(hv), hp);
                else   hv = __halves2half2(hp, __high2half(hv));
                memcpy(&reg, &hv, 4);
                acc[mi][nt][h] = reg;
            }

            uint32_t s2 = 0;
            #pragma unroll
            for (int ni = 0; ni < 4; ni++)
                s2 = hadd2(s2, ex2_h2(hfma2_(acc[mi][ni][h], rw2p[ni], b2p[ni])));
            s2 = hadd2(s2, swap16(s2));
            __half2 sh; memcpy(&sh, &s2, 4);
            float p = __low2float(sh);
            p += __shfl_xor_sync(0xffffffffu, p, 1);
            p += __shfl_xor_sync(0xffffffffu, p, 2);
            if (tig == 0) atomicAdd(&rowacc[r], p);
        }
    }
    __syncthreads();
    if (tid < 128) atomicAdd(&g_rowsum[row0 + tid], rowacc[tid]);
}

// ---------------------------------------------------------------------------
__global__ void finalize_kernel(float* __restrict__ out) {
    int i = threadIdx.x;   // 512
    float v = logf(g_rowsum[i]) + SHIFT_LN - g_tlogit[i];
    #pragma unroll
    for (int o = 16; o; o >>= 1) v += __shfl_xor_sync(0xffffffffu, v, o);
    __shared__ float sm[16];
    if ((i & 31) == 0) sm[i >> 5] = v;
    __syncthreads();
    if (i < 16) {
        float t = sm[i];
        #pragma unroll
        for (int o = 8; o; o >>= 1) t += __shfl_xor_sync(0x0000ffffu, t, o);
        if (i == 0) out[0] = t * (1.0f / (float)N_);
    }
}

// ---------------------------------------------------------------------------
extern "C" void kernel_launch(void* const* d_in, const int* in_sizes, int n_in,
                              void* d_out, int out_size) {
    const float* x   = (const float*)d_in[0];   // [512, 512] fp32
    const int*   tgt = (const int*)d_in[1];     // [512] int32
    const float* w   = (const float*)d_in[2];   // [100000, 512] fp32

    static int smem_set = 0;
    if (!smem_set) {
        cudaFuncSetAttribute(arcface_gemm_kernel,
                             cudaFuncAttributeMaxDynamicSharedMemorySize, SMEM_BYTES);
        smem_set = 1;
    }

    norm_x_kernel<<<256, 256>>>(x);
    dim3 grid(4, (C_ + 127) / 128);
    arcface_gemm_kernel<<<grid, 256, SMEM_BYTES>>>(w, tgt);
    finalize_kernel<<<1, N_>>>((float*)d_out);
}